// round 2
// baseline (speedup 1.0000x reference)
#include <cuda_runtime.h>
#include <cuda_bf16.h>

#define NN 100000
#define NE 1600000
#define FIN 128
#define DH 32        // D*H
#define GH 64
#define HH 16
#define NOUT 10

// ---------------- scratch (device globals; no allocation) ----------------
__device__ __align__(16) float g_h[NN * DH];        // h, later xs (N,2,16)
__device__ __align__(16) float g_m[NN * GH];        // sheaf-learner hidden
__device__ __align__(16) float g_agg64[NN * GH];    // segment-sum scratch (GH)
__device__ __align__(16) float g_agg32[NN * DH];    // segment-sum scratch (DH)
__device__ float g_deg[NN];
__device__ float2 g_cs[NN];                          // (cos, sin) per node
__device__ int g_src[NE];
__device__ int g_dst[NE];
__device__ __align__(8) float2 g_ab[NE];             // (cos*norm, sin*norm) per edge
__device__ int g_idx64;                              // 1 if edge buffer is int64

// ---------------- helpers ----------------
__device__ __forceinline__ float gelu_f(float v) {
    // jax.nn.gelu approximate=True (tanh form)
    const float c = 0.7978845608028654f;
    float t = tanhf(c * (v + 0.044715f * v * v * v));
    return 0.5f * v * (1.0f + t);
}

__device__ __forceinline__ void red4(float* p, float4 v) {
#if __CUDA_ARCH__ >= 900
    atomicAdd(reinterpret_cast<float4*>(p), v);
#else
    atomicAdd(p + 0, v.x); atomicAdd(p + 1, v.y);
    atomicAdd(p + 2, v.z); atomicAdd(p + 3, v.w);
#endif
}

// ---------------- kernels ----------------

// probe edge-index dtype: int64 layout => odd 32-bit words (high halves) all zero
__global__ void k_probe(const unsigned int* __restrict__ w) {
    if (blockIdx.x == 0 && threadIdx.x == 0) {
        int is64 = 1;
        for (int i = 0; i < 256; i++) {
            if (w[2 * i + 1] != 0u) { is64 = 0; break; }
        }
        g_idx64 = is64;
    }
}

// zero agg buffers, deg = 1 (self-loop)
__global__ void k_init() {
    int i = blockIdx.x * blockDim.x + threadIdx.x;
    if (i < NN * GH) g_agg64[i] = 0.0f;
    if (i < NN * DH) g_agg32[i] = 0.0f;
    if (i < NN)      g_deg[i] = 1.0f;
}

// decode edge indices (int32 or int64), clamp, accumulate degree(dst)
__global__ void k_prep(const void* __restrict__ ei) {
    int e = blockIdx.x * blockDim.x + threadIdx.x;
    if (e >= NE) return;
    int s, d;
    if (g_idx64) {
        const long long* p = (const long long*)ei;
        s = (int)p[e];
        d = (int)p[NE + e];
    } else {
        const int* p = (const int*)ei;
        s = p[e];
        d = p[NE + e];
    }
    s = min(max(s, 0), NN - 1);
    d = min(max(d, 0), NN - 1);
    g_src[e] = s;
    g_dst[e] = d;
    atomicAdd(&g_deg[d], 1.0f);
}

// h = x@W_in + b_in ; m = gelu(h@emb1_W + emb1_b). 8 nodes per 256-thread block.
__global__ __launch_bounds__(256) void k_embed(
    const float* __restrict__ x, const float* __restrict__ W_in,
    const float* __restrict__ b_in, const float* __restrict__ emb1_W,
    const float* __restrict__ emb1_b)
{
    __shared__ float sx[8][FIN];
    __shared__ float sh[8][DH];
    int base = blockIdx.x * 8;
    for (int i = threadIdx.x; i < 8 * FIN; i += 256) {
        int nl = i >> 7, k = i & 127;
        int n = base + nl;
        sx[nl][k] = (n < NN) ? x[(size_t)n * FIN + k] : 0.0f;
    }
    __syncthreads();
    {
        int nl = threadIdx.x >> 5;
        int t  = threadIdx.x & 31;
        float acc = b_in[t];
        #pragma unroll 8
        for (int k = 0; k < FIN; k++) acc += sx[nl][k] * W_in[k * DH + t];
        sh[nl][t] = acc;
        int n = base + nl;
        if (n < NN) g_h[n * DH + t] = acc;
    }
    __syncthreads();
    for (int i = threadIdx.x; i < 8 * GH; i += 256) {
        int nl = i >> 6, j = i & 63;
        float acc = emb1_b[j];
        #pragma unroll
        for (int q = 0; q < DH; q++) acc += sh[nl][q] * emb1_W[q * GH + j];
        int n = base + nl;
        if (n < NN) g_m[n * GH + j] = gelu_f(acc);
    }
}

// scatter m[src] into agg64[dst]: 16 threads/edge, float4 each
__global__ __launch_bounds__(256) void k_scatter64() {
    int tid = blockIdx.x * blockDim.x + threadIdx.x;
    if (tid >= NE * 16) return;
    int e = tid >> 4, q = tid & 15;
    int s = g_src[e], d = g_dst[e];
    float4 v = ((const float4*)g_m)[s * 16 + q];
    red4(&g_agg64[d * GH + q * 4], v);
}

// m = gelu(m@Ws + agg@Wn); zero agg row for next pass. 16 nodes / 256-thread block.
__global__ __launch_bounds__(256) void k_update_m(
    const float* __restrict__ Ws, const float* __restrict__ Wn)
{
    __shared__ float sWs[GH * GH];
    __shared__ float sWn[GH * GH];
    __shared__ float sm[16 * GH];
    __shared__ float sa[16 * GH];
    int base = blockIdx.x * 16;
    for (int i = threadIdx.x; i < GH * GH; i += 256) {
        sWs[i] = Ws[i];
        sWn[i] = Wn[i];
    }
    for (int i = threadIdx.x; i < 16 * GH; i += 256) {
        int n = base + (i >> 6);
        sm[i] = (n < NN) ? g_m[(size_t)base * GH + i] : 0.0f;
        sa[i] = (n < NN) ? g_agg64[(size_t)base * GH + i] : 0.0f;
    }
    __syncthreads();
    for (int o = threadIdx.x; o < 16 * GH; o += 256) {
        int nl = o >> 6, j = o & 63;
        float acc = 0.0f;
        #pragma unroll 8
        for (int i = 0; i < GH; i++)
            acc += sm[nl * GH + i] * sWs[i * GH + j] + sa[nl * GH + i] * sWn[i * GH + j];
        int n = base + nl;
        if (n < NN) {
            g_m[n * GH + j] = gelu_f(acc);
            g_agg64[n * GH + j] = 0.0f;   // prep next scatter
        }
    }
}

// theta = tanh(m@emb2_W + b); store (cos, sin) of 2*pi*theta. warp per node.
__global__ __launch_bounds__(128) void k_theta(
    const float* __restrict__ w2, const float* __restrict__ b2)
{
    int warp = threadIdx.x >> 5;
    int lane = threadIdx.x & 31;
    int n = blockIdx.x * 4 + warp;
    if (n >= NN) return;
    float acc = g_m[n * GH + lane] * w2[lane] + g_m[n * GH + 32 + lane] * w2[32 + lane];
    #pragma unroll
    for (int off = 16; off > 0; off >>= 1)
        acc += __shfl_xor_sync(0xFFFFFFFFu, acc, off);
    if (lane == 0) {
        float t = tanhf(acc + b2[0]);
        float ang = t * 6.283185307179586f;
        float s, c;
        sincosf(ang, &s, &c);
        g_cs[n] = make_float2(c, s);
    }
}

// per-edge transport coefficients: R_dst^T R_src = R(theta_s - theta_d), scaled by norm
__global__ __launch_bounds__(256) void k_coeff() {
    int e = blockIdx.x * blockDim.x + threadIdx.x;
    if (e >= NE) return;
    int s = g_src[e], d = g_dst[e];
    float2 cs = g_cs[s], cd = g_cs[d];
    float cm = cd.x * cs.x + cd.y * cs.y;   // cos(ts - td)
    float sm = cd.x * cs.y - cd.y * cs.x;   // sin(ts - td)
    float nrm = rsqrtf(g_deg[s] * g_deg[d]);
    g_ab[e] = make_float2(cm * nrm, sm * nrm);
}

// diffusion scatter: msg = M_e @ xs[src] * norm -> agg32[dst]. 4 threads/edge.
__global__ __launch_bounds__(256) void k_diff_scatter() {
    int tid = blockIdx.x * blockDim.x + threadIdx.x;
    if (tid >= NE * 4) return;
    int e = tid >> 2, q = tid & 3;
    int s = g_src[e], d = g_dst[e];
    float2 ab = g_ab[e];
    const float4* xs4 = (const float4*)g_h;
    float4 x0 = xs4[s * 8 + q];       // d=0 components, 4 h's
    float4 x1 = xs4[s * 8 + 4 + q];   // d=1 components
    float4 m0, m1;
    m0.x = ab.x * x0.x - ab.y * x1.x;  m1.x = ab.y * x0.x + ab.x * x1.x;
    m0.y = ab.x * x0.y - ab.y * x1.y;  m1.y = ab.y * x0.y + ab.x * x1.y;
    m0.z = ab.x * x0.z - ab.y * x1.z;  m1.z = ab.y * x0.z + ab.x * x1.z;
    m0.w = ab.x * x0.w - ab.y * x1.w;  m1.w = ab.y * x0.w + ab.x * x1.w;
    red4(&g_agg32[d * DH + q * 4], m0);
    red4(&g_agg32[d * DH + 16 + q * 4], m1);
}

// xs = xs - gelu((xs - agg) @ W_diff[l]); zero agg row. 8 nodes / 256-thread block.
__global__ __launch_bounds__(256) void k_diff_update(const float* __restrict__ W) {
    __shared__ float sW[HH * HH];
    __shared__ float sxs[8][DH];
    __shared__ float sag[8][DH];
    int base = blockIdx.x * 8;
    if (threadIdx.x < HH * HH) sW[threadIdx.x] = W[threadIdx.x];
    {
        int i = threadIdx.x;             // 256 = 8*32 exactly
        int nl = i >> 5, c = i & 31;
        int n = base + nl;
        sxs[nl][c] = (n < NN) ? g_h[n * DH + c] : 0.0f;
        sag[nl][c] = (n < NN) ? g_agg32[n * DH + c] : 0.0f;
    }
    __syncthreads();
    {
        int i = threadIdx.x;
        int nl = i >> 5, idx = i & 31;
        int dd = idx >> 4, k = idx & 15;
        float acc = 0.0f;
        #pragma unroll
        for (int h = 0; h < HH; h++) {
            float lx = sxs[nl][dd * HH + h] - sag[nl][dd * HH + h];
            acc += lx * sW[h * HH + k];
        }
        int n = base + nl;
        if (n < NN) {
            g_h[n * DH + idx] = sxs[nl][idx] - gelu_f(acc);
            g_agg32[n * DH + idx] = 0.0f;   // prep next layer / replay
        }
    }
}

// out = xs @ W_out + b_out
__global__ __launch_bounds__(256) void k_out(
    const float* __restrict__ W_out, const float* __restrict__ b_out,
    float* __restrict__ out)
{
    int gid = blockIdx.x * blockDim.x + threadIdx.x;
    if (gid >= NN * NOUT) return;
    int n = gid / NOUT, o = gid - n * NOUT;
    float acc = b_out[o];
    #pragma unroll 8
    for (int i = 0; i < DH; i++) acc += g_h[n * DH + i] * W_out[i * NOUT + o];
    out[gid] = acc;
}

// ---------------- launch ----------------
extern "C" void kernel_launch(void* const* d_in, const int* in_sizes, int n_in,
                              void* d_out, int out_size) {
    // Size-based detection for the two unambiguous big inputs.
    int i_x = 0, i_ei = 1;
    for (int i = 0; i < n_in; i++) {
        if (in_sizes[i] == NN * FIN)  i_x = i;
        if (in_sizes[i] == 2 * NE)    i_ei = i;
    }
    const float* x  = (const float*)d_in[i_x];
    const void*  ei = d_in[i_ei];
    const float* W_in    = (const float*)d_in[2];
    const float* b_in    = (const float*)d_in[3];
    const float* emb1_W  = (const float*)d_in[4];
    const float* emb1_b  = (const float*)d_in[5];
    const float* Ws1     = (const float*)d_in[6];
    const float* Wn1     = (const float*)d_in[7];
    const float* Ws2     = (const float*)d_in[8];
    const float* Wn2     = (const float*)d_in[9];
    const float* emb2_W  = (const float*)d_in[10];
    const float* emb2_b  = (const float*)d_in[11];
    const float* W_diff  = (const float*)d_in[12];
    const float* W_out   = (const float*)d_in[13];
    const float* b_out   = (const float*)d_in[14];
    float* out = (float*)d_out;

    k_probe<<<1, 32>>>((const unsigned int*)ei);
    k_init<<<(NN * GH + 255) / 256, 256>>>();
    k_prep<<<(NE + 255) / 256, 256>>>(ei);
    k_embed<<<(NN + 7) / 8, 256>>>(x, W_in, b_in, emb1_W, emb1_b);

    // SumGNN layer 1
    k_scatter64<<<(NE * 16 + 255) / 256, 256>>>();
    k_update_m<<<(NN + 15) / 16, 256>>>(Ws1, Wn1);
    // SumGNN layer 2
    k_scatter64<<<(NE * 16 + 255) / 256, 256>>>();
    k_update_m<<<(NN + 15) / 16, 256>>>(Ws2, Wn2);

    k_theta<<<(NN + 3) / 4, 128>>>(emb2_W, emb2_b);
    k_coeff<<<(NE + 255) / 256, 256>>>();

    // diffusion layers
    for (int l = 0; l < 2; l++) {
        k_diff_scatter<<<(NE * 4 + 255) / 256, 256>>>();
        k_diff_update<<<(NN + 7) / 8, 256>>>(W_diff + l * HH * HH);
    }

    k_out<<<(NN * NOUT + 255) / 256, 256>>>(W_out, b_out, out);
}